// round 6
// baseline (speedup 1.0000x reference)
#include <cuda_runtime.h>
#include <math.h>

// Fixed shapes per reference
#define N_PTS 262144
#define B_ 4
#define T_ 4
#define P_ 512
#define R_ 256
#define C_ 64
#define H_ 512
#define W_ 512
#define HW_ (H_ * W_)
#define RC_ (R_ * C_)
#define PRC_ (P_ * RC_)

#define COPY_BLOCKS 16384
#define SCATTER_BLOCKS (N_PTS / 16)       // 16 points per 256-thread block
#define OUT_ELEMS (B_ * C_ * HW_)         // 67108864 floats
#define SCRATCH_ELEMS (B_ * H_ * T_ * C_) // 524288 floats (2MB, L2-resident)

// Compact privatized accumulator: [b][y][t][c] — channel-contiguous so the
// scatter atomics are coalesced (vs 1MB-strided in the output layout).
__device__ float g_scratch[SCRATCH_ELEMS];

__device__ __forceinline__ void red_add_v4(float* p, float4 v) {
    asm volatile("red.global.add.v4.f32 [%0], {%1,%2,%3,%4};"
                 :: "l"(p), "f"(v.x), "f"(v.y), "f"(v.z), "f"(v.w)
                 : "memory");
}

// One fused kernel: blocks [0, COPY_BLOCKS) stream-copy spatial->out,
// blocks [COPY_BLOCKS, ...) do the gather + coalesced scatter into scratch.
// Fusing overlaps the copy's streaming DRAM traffic with the gather's
// latency-bound DRAM traffic.
__global__ void __launch_bounds__(256) pp_fused_kernel(
    const int4*  __restrict__ coords,
    const float* __restrict__ pview,
    const float4* __restrict__ spatial4,
    float4* __restrict__ out4)
{
    const int tid = threadIdx.x;

    if (blockIdx.x < COPY_BLOCKS) {
        // ---- copy path: 256MB out = spatial ----
        int idx = blockIdx.x * 256 + tid;
        const int stride = COPY_BLOCKS * 256;          // 4194304
        #pragma unroll
        for (int i = 0; i < 4; i++) {
            out4[idx] = spatial4[idx];
            idx += stride;
        }
        return;
    }

    // ---- scatter path: 16 lanes per point, float4 per lane ----
    const int warp   = tid >> 5;
    const int half   = (tid >> 4) & 1;
    const int lane16 = tid & 15;
    const int pt = (blockIdx.x - COPY_BLOCKS) * 16 + warp * 2 + half;

    int4 c = coords[pt];
    const int b = c.x, t = c.y, yy = c.z, xx = c.w;

    // Replicate reference float32 math exactly (no FMA contraction) so the
    // xf==0 special case matches bit-for-bit.
    float yf = __fadd_rn(__fmul_rn((float)yy, 0.2f), -51.2f);
    float xf = __fadd_rn(__fmul_rn((float)xx, 0.2f), -51.2f);

    float r = sqrtf(__fadd_rn(__fmul_rn(xf, xf), __fmul_rn(yf, yf)));
    float psi;
    if (xf == 0.0f && yf >= 0.0f) {
        psi = 1.57079632679489662f;       // pi/2
    } else {
        psi = atan2f(yf, xf);
    }

    float r_idx = __fdiv_rn(r, 0.3f);
    float p_idx = __fdiv_rn(__fadd_rn(psi, 3.14159265358979323846f),
                            0.012566370614359172f);

    int r0i = (int)floorf(r_idx);
    int p0i = (int)floorf(p_idx);
    // t frac is exactly 0 (integer cast to float) -> t+1 corner weight == 0.

    const float fr = r_idx - (float)r0i;
    const float fp = p_idx - (float)p0i;

    const int r0 = r0i * C_;
    const int r1 = min(r0i + 1, R_ - 1) * C_;
    const int p0 = p0i * RC_;
    const int p1 = min(p0i + 1, P_ - 1) * RC_;

    const float* base = pview + (b * T_ + t) * PRC_ + 4 * lane16;

    float4 v00 = *(const float4*)(base + p0 + r0);
    float4 v01 = *(const float4*)(base + p0 + r1);
    float4 v10 = *(const float4*)(base + p1 + r0);
    float4 v11 = *(const float4*)(base + p1 + r1);

    const float wr0 = 1.0f - fr, wr1 = fr;
    const float wp0 = 1.0f - fp, wp1 = fp;

    float4 acc;
    acc.x = wp0 * (wr0 * v00.x + wr1 * v01.x) + wp1 * (wr0 * v10.x + wr1 * v11.x);
    acc.y = wp0 * (wr0 * v00.y + wr1 * v01.y) + wp1 * (wr0 * v10.y + wr1 * v11.y);
    acc.z = wp0 * (wr0 * v00.z + wr1 * v01.z) + wp1 * (wr0 * v10.z + wr1 * v11.z);
    acc.w = wp0 * (wr0 * v00.w + wr1 * v01.w) + wp1 * (wr0 * v10.w + wr1 * v11.w);

    // Coalesced fire-and-forget v4 reduction into the 2MB L2-resident scratch.
    float* dst = g_scratch + ((b * H_ + yy) * T_ + t) * C_ + 4 * lane16;
    red_add_v4(dst, acc);
}

// Epilogue: transpose-add scratch[b][y][t][c] into out[b][c][y][t].
__global__ void __launch_bounds__(256) pp_add_kernel(float* __restrict__ out)
{
    int idx = blockIdx.x * 256 + threadIdx.x;   // linear over scratch (coalesced read)
    float v = g_scratch[idx];
    const int ch  = idx & (C_ - 1);
    int rest = idx >> 6;                        // ((b*H + y)*T + t)
    const int t  = rest & (T_ - 1);
    rest >>= 2;                                 // b*H + y
    const int y  = rest & (H_ - 1);
    const int b  = rest >> 9;
    out[b * (C_ * HW_) + ch * HW_ + y * W_ + t] += v;
}

extern "C" void kernel_launch(void* const* d_in, const int* in_sizes, int n_in,
                              void* d_out, int out_size) {
    const int*   coords  = (const int*)d_in[0];   // voxel_coords [N,4] int32
    const float* pview   = (const float*)d_in[1]; // [B,T,P,R,C] f32
    const float* spatial = (const float*)d_in[2]; // [B,C,H,W] f32
    float* out = (float*)d_out;

    // Zero the privatized accumulator (2MB memset node; graph-capturable).
    void* scratch_ptr = nullptr;
    cudaGetSymbolAddress(&scratch_ptr, g_scratch);
    cudaMemsetAsync(scratch_ptr, 0, SCRATCH_ELEMS * sizeof(float), 0);

    pp_fused_kernel<<<COPY_BLOCKS + SCATTER_BLOCKS, 256>>>(
        (const int4*)coords, pview, (const float4*)spatial, (float4*)out);

    pp_add_kernel<<<SCRATCH_ELEMS / 256, 256>>>(out);
}

// round 7
// speedup vs baseline: 1.0282x; 1.0282x over previous
#include <cuda_runtime.h>
#include <math.h>

// Fixed shapes per reference
#define N_PTS 262144
#define B_ 4
#define T_ 4
#define P_ 512
#define R_ 256
#define C_ 64
#define H_ 512
#define W_ 512
#define HW_ (H_ * W_)
#define RC_ (R_ * C_)
#define PRC_ (P_ * RC_)

#define COPY_BLOCKS 16384
#define SCATTER_BLOCKS (N_PTS / 16)       // 16 points per 256-thread block
#define SCRATCH_ELEMS (B_ * H_ * T_ * C_) // 524288 floats (2MB, L2-resident)

// Compact privatized accumulator: [b][y][t][c] — channel-contiguous so the
// scatter atomics are coalesced. Zero-initialized (BSS); the epilogue re-zeros
// it after consuming, so no memset node is needed and every graph replay sees
// a zeroed scratch (deterministic invariant).
__device__ float g_scratch[SCRATCH_ELEMS];

__device__ __forceinline__ void red_add_v4(float* p, float4 v) {
    asm volatile("red.global.add.v4.f32 [%0], {%1,%2,%3,%4};"
                 :: "l"(p), "f"(v.x), "f"(v.y), "f"(v.z), "f"(v.w)
                 : "memory");
}

// One fused kernel: blocks [0, COPY_BLOCKS) stream-copy spatial->out,
// blocks [COPY_BLOCKS, ...) do the gather + coalesced scatter into scratch.
// Fusing overlaps the copy's streaming DRAM traffic with the gather's
// latency-bound DRAM traffic.
__global__ void __launch_bounds__(256) pp_fused_kernel(
    const int4*  __restrict__ coords,
    const float* __restrict__ pview,
    const float4* __restrict__ spatial4,
    float4* __restrict__ out4)
{
    const int tid = threadIdx.x;

    if (blockIdx.x < COPY_BLOCKS) {
        // ---- copy path: 256MB out = spatial ----
        int idx = blockIdx.x * 256 + tid;
        const int stride = COPY_BLOCKS * 256;          // 4194304
        #pragma unroll
        for (int i = 0; i < 4; i++) {
            out4[idx] = spatial4[idx];
            idx += stride;
        }
        return;
    }

    // ---- scatter path: 16 lanes per point, float4 per lane ----
    const int warp   = tid >> 5;
    const int half   = (tid >> 4) & 1;
    const int lane16 = tid & 15;
    const int pt = (blockIdx.x - COPY_BLOCKS) * 16 + warp * 2 + half;

    int4 c = coords[pt];
    const int b = c.x, t = c.y, yy = c.z, xx = c.w;

    // Replicate reference float32 math exactly (no FMA contraction) so the
    // xf==0 special case matches bit-for-bit.
    float yf = __fadd_rn(__fmul_rn((float)yy, 0.2f), -51.2f);
    float xf = __fadd_rn(__fmul_rn((float)xx, 0.2f), -51.2f);

    float r = sqrtf(__fadd_rn(__fmul_rn(xf, xf), __fmul_rn(yf, yf)));
    float psi;
    if (xf == 0.0f && yf >= 0.0f) {
        psi = 1.57079632679489662f;       // pi/2
    } else {
        psi = atan2f(yf, xf);
    }

    float r_idx = __fdiv_rn(r, 0.3f);
    float p_idx = __fdiv_rn(__fadd_rn(psi, 3.14159265358979323846f),
                            0.012566370614359172f);

    int r0i = (int)floorf(r_idx);
    int p0i = (int)floorf(p_idx);
    // t frac is exactly 0 (integer cast to float) -> t+1 corner weight == 0.

    const float fr = r_idx - (float)r0i;
    const float fp = p_idx - (float)p0i;

    const int r0 = r0i * C_;
    const int r1 = min(r0i + 1, R_ - 1) * C_;
    const int p0 = p0i * RC_;
    const int p1 = min(p0i + 1, P_ - 1) * RC_;

    const float* base = pview + (b * T_ + t) * PRC_ + 4 * lane16;

    float4 v00 = *(const float4*)(base + p0 + r0);
    float4 v01 = *(const float4*)(base + p0 + r1);
    float4 v10 = *(const float4*)(base + p1 + r0);
    float4 v11 = *(const float4*)(base + p1 + r1);

    const float wr0 = 1.0f - fr, wr1 = fr;
    const float wp0 = 1.0f - fp, wp1 = fp;

    float4 acc;
    acc.x = wp0 * (wr0 * v00.x + wr1 * v01.x) + wp1 * (wr0 * v10.x + wr1 * v11.x);
    acc.y = wp0 * (wr0 * v00.y + wr1 * v01.y) + wp1 * (wr0 * v10.y + wr1 * v11.y);
    acc.z = wp0 * (wr0 * v00.z + wr1 * v01.z) + wp1 * (wr0 * v10.z + wr1 * v11.z);
    acc.w = wp0 * (wr0 * v00.w + wr1 * v01.w) + wp1 * (wr0 * v10.w + wr1 * v11.w);

    // Coalesced fire-and-forget v4 reduction into the 2MB L2-resident scratch.
    float* dst = g_scratch + ((b * H_ + yy) * T_ + t) * C_ + 4 * lane16;
    red_add_v4(dst, acc);
}

// Epilogue: one thread per (b, y, c) handles all 4 t values.
//  - scratch reads are coalesced (c consecutive across lanes), 4 per thread
//  - scratch is zeroed back in place (replaces the memset node)
//  - out RMW is a single float4 load+store (t=0..3 contiguous, 16B-aligned)
__global__ void __launch_bounds__(256) pp_add_kernel(float* __restrict__ out)
{
    const int idx = blockIdx.x * 256 + threadIdx.x;  // (b, y, c) flat
    const int ch = idx & (C_ - 1);
    const int y  = (idx >> 6) & (H_ - 1);
    const int b  = idx >> 15;

    // scratch[((b*H + y)*T + t)*C + ch], t = 0..3 -> stride C_
    const int sbase = ((b * H_ + y) * T_) * C_ + ch;
    float v0 = g_scratch[sbase];
    float v1 = g_scratch[sbase + C_];
    float v2 = g_scratch[sbase + 2 * C_];
    float v3 = g_scratch[sbase + 3 * C_];

    g_scratch[sbase]          = 0.0f;
    g_scratch[sbase + C_]     = 0.0f;
    g_scratch[sbase + 2 * C_] = 0.0f;
    g_scratch[sbase + 3 * C_] = 0.0f;

    float4* dst = (float4*)(out + b * (C_ * HW_) + ch * HW_ + y * W_);
    float4 o = *dst;
    o.x += v0; o.y += v1; o.z += v2; o.w += v3;
    *dst = o;
}

extern "C" void kernel_launch(void* const* d_in, const int* in_sizes, int n_in,
                              void* d_out, int out_size) {
    const int*   coords  = (const int*)d_in[0];   // voxel_coords [N,4] int32
    const float* pview   = (const float*)d_in[1]; // [B,T,P,R,C] f32
    const float* spatial = (const float*)d_in[2]; // [B,C,H,W] f32
    float* out = (float*)d_out;

    pp_fused_kernel<<<COPY_BLOCKS + SCATTER_BLOCKS, 256>>>(
        (const int4*)coords, pview, (const float4*)spatial, (float4*)out);

    pp_add_kernel<<<(B_ * H_ * C_) / 256, 256>>>(out);
}

// round 8
// speedup vs baseline: 1.0328x; 1.0045x over previous
#include <cuda_runtime.h>
#include <math.h>

// Fixed shapes per reference
#define N_PTS 262144
#define B_ 4
#define T_ 4
#define P_ 512
#define R_ 256
#define C_ 64
#define H_ 512
#define W_ 512
#define HW_ (H_ * W_)
#define RC_ (R_ * C_)
#define PRC_ (P_ * RC_)

#define COPY_BLOCKS 16384
#define SCATTER_BLOCKS (N_PTS / 16)       // 16 points per 256-thread block
#define SCRATCH_ELEMS (B_ * H_ * T_ * C_) // 524288 floats (2MB, L2-resident)

// Compact privatized accumulator: [b][y][t][c] — channel-contiguous so the
// scatter atomics are coalesced. Zero-initialized (BSS); the epilogue re-zeros
// it after consuming, so no memset node is needed and every graph replay sees
// a zeroed scratch (deterministic invariant).
__device__ float g_scratch[SCRATCH_ELEMS];

__device__ __forceinline__ void red_add_v4(float* p, float4 v) {
    asm volatile("red.global.add.v4.f32 [%0], {%1,%2,%3,%4};"
                 :: "l"(p), "f"(v.x), "f"(v.y), "f"(v.z), "f"(v.w)
                 : "memory");
}

// One fused kernel: blocks [0, COPY_BLOCKS) stream-copy spatial->out,
// blocks [COPY_BLOCKS, ...) do the gather + coalesced scatter into scratch.
// Fusing overlaps the copy's streaming DRAM traffic with the gather's
// latency-bound DRAM traffic.
__global__ void __launch_bounds__(256) pp_fused_kernel(
    const int4*  __restrict__ coords,
    const float* __restrict__ pview,
    const float4* __restrict__ spatial4,
    float4* __restrict__ out4)
{
    const int tid = threadIdx.x;

    if (blockIdx.x < COPY_BLOCKS) {
        // ---- copy path: 256MB out = spatial ----
        int idx = blockIdx.x * 256 + tid;
        const int stride = COPY_BLOCKS * 256;          // 4194304
        #pragma unroll
        for (int i = 0; i < 4; i++) {
            out4[idx] = spatial4[idx];
            idx += stride;
        }
        return;
    }

    // ---- scatter path: 16 lanes per point, float4 per lane ----
    const int warp   = tid >> 5;
    const int half   = (tid >> 4) & 1;
    const int lane16 = tid & 15;
    const int pt = (blockIdx.x - COPY_BLOCKS) * 16 + warp * 2 + half;

    int4 c = coords[pt];
    const int b = c.x, t = c.y, yy = c.z, xx = c.w;

    // Replicate reference float32 math exactly (no FMA contraction) so the
    // xf==0 special case matches bit-for-bit.
    float yf = __fadd_rn(__fmul_rn((float)yy, 0.2f), -51.2f);
    float xf = __fadd_rn(__fmul_rn((float)xx, 0.2f), -51.2f);

    float r = sqrtf(__fadd_rn(__fmul_rn(xf, xf), __fmul_rn(yf, yf)));
    float psi;
    if (xf == 0.0f && yf >= 0.0f) {
        psi = 1.57079632679489662f;       // pi/2
    } else {
        psi = atan2f(yf, xf);
    }

    float r_idx = __fdiv_rn(r, 0.3f);
    float p_idx = __fdiv_rn(__fadd_rn(psi, 3.14159265358979323846f),
                            0.012566370614359172f);

    int r0i = (int)floorf(r_idx);
    int p0i = (int)floorf(p_idx);
    // t frac is exactly 0 (integer cast to float) -> t+1 corner weight == 0.

    const float fr = r_idx - (float)r0i;
    const float fp = p_idx - (float)p0i;

    const int r0 = r0i * C_;
    const int r1 = min(r0i + 1, R_ - 1) * C_;
    const int p0 = p0i * RC_;
    const int p1 = min(p0i + 1, P_ - 1) * RC_;

    const float* base = pview + (b * T_ + t) * PRC_ + 4 * lane16;

    float4 v00 = *(const float4*)(base + p0 + r0);
    float4 v01 = *(const float4*)(base + p0 + r1);
    float4 v10 = *(const float4*)(base + p1 + r0);
    float4 v11 = *(const float4*)(base + p1 + r1);

    const float wr0 = 1.0f - fr, wr1 = fr;
    const float wp0 = 1.0f - fp, wp1 = fp;

    float4 acc;
    acc.x = wp0 * (wr0 * v00.x + wr1 * v01.x) + wp1 * (wr0 * v10.x + wr1 * v11.x);
    acc.y = wp0 * (wr0 * v00.y + wr1 * v01.y) + wp1 * (wr0 * v10.y + wr1 * v11.y);
    acc.z = wp0 * (wr0 * v00.z + wr1 * v01.z) + wp1 * (wr0 * v10.z + wr1 * v11.z);
    acc.w = wp0 * (wr0 * v00.w + wr1 * v01.w) + wp1 * (wr0 * v10.w + wr1 * v11.w);

    // Coalesced fire-and-forget v4 reduction into the 2MB L2-resident scratch.
    float* dst = g_scratch + ((b * H_ + yy) * T_ + t) * C_ + 4 * lane16;
    red_add_v4(dst, acc);
}

// Epilogue: one thread per (b, y, c) handles all 4 t values.
//  - scratch reads are L2-hot (just written by the scatter atomics)
//  - scratch is zeroed back in place (replaces the memset node)
//  - out update is a fire-and-forget red.v4: NO dependent DRAM read on the
//    critical path (the old ld+add+st RMW stalled ~600-1000cyc on a DRAM load
//    of just-evicted out lines; LTS now does the RMW asynchronously)
__global__ void __launch_bounds__(256) pp_add_kernel(float* __restrict__ out)
{
    const int idx = blockIdx.x * 256 + threadIdx.x;  // (b, y, c) flat
    const int ch = idx & (C_ - 1);
    const int y  = (idx >> 6) & (H_ - 1);
    const int b  = idx >> 15;

    // scratch[((b*H + y)*T + t)*C + ch], t = 0..3 -> stride C_
    const int sbase = ((b * H_ + y) * T_) * C_ + ch;
    float v0 = g_scratch[sbase];
    float v1 = g_scratch[sbase + C_];
    float v2 = g_scratch[sbase + 2 * C_];
    float v3 = g_scratch[sbase + 3 * C_];

    g_scratch[sbase]          = 0.0f;
    g_scratch[sbase + C_]     = 0.0f;
    g_scratch[sbase + 2 * C_] = 0.0f;
    g_scratch[sbase + 3 * C_] = 0.0f;

    float4 v = make_float4(v0, v1, v2, v3);
    // out[b][ch][y][0..3] — 16B-aligned (base is a multiple of 512 floats)
    red_add_v4(out + b * (C_ * HW_) + ch * HW_ + y * W_, v);
}

extern "C" void kernel_launch(void* const* d_in, const int* in_sizes, int n_in,
                              void* d_out, int out_size) {
    const int*   coords  = (const int*)d_in[0];   // voxel_coords [N,4] int32
    const float* pview   = (const float*)d_in[1]; // [B,T,P,R,C] f32
    const float* spatial = (const float*)d_in[2]; // [B,C,H,W] f32
    float* out = (float*)d_out;

    pp_fused_kernel<<<COPY_BLOCKS + SCATTER_BLOCKS, 256>>>(
        (const int4*)coords, pview, (const float4*)spatial, (float4*)out);

    pp_add_kernel<<<(B_ * H_ * C_) / 256, 256>>>(out);
}